// round 11
// baseline (speedup 1.0000x reference)
#include <cuda_runtime.h>

namespace {

constexpr int Bn = 16;
constexpr int Ln = 2048;
constexpr int Gn = 8;
constexpr int Pn = 8;
constexpr int Kn = 64;
constexpr float kClamp = 15.0f;

constexpr int LT = 256;             // l's per block
constexpr int NPAIR = LT / 2;       // 128 l-pairs
constexpr int NTb = Ln / LT;        // 8 tiles per batch
constexpr int GRID = Bn * NTb;      // 128 blocks <= 148 SMs: residency GUARANTEED
constexpr int NKQ = 8;              // k-split ways
constexpr int KQ = Kn / NKQ;        // 8 k per thread
constexpr int THREADS = NPAIR * NKQ;// 1024
constexpr int NW = THREADS / 32;    // 32 warps
constexpr int DN_BYTES = Kn * LT * 4;   // 64 KB dynamic smem for dn

__device__ float g_partial[2][Bn][NTb][Pn];
__device__ unsigned g_cnt[Bn * 32];
__device__ unsigned g_gen[Bn * 32];

__device__ __forceinline__ float vldf(const float* p) { return *(volatile const float*)p; }

// Barrier over the NTb blocks of one batch only. Safe: grid <= #SMs, so all
// blocks are always resident regardless of occupancy.
__device__ __forceinline__ void batch_sync(int b) {
    __syncthreads();
    if (threadIdx.x == 0) {
        __threadfence();
        volatile unsigned* genv = (volatile unsigned*)&g_gen[b * 32];
        unsigned cur = *genv;                       // snapshot BEFORE arrive
        if (atomicAdd(&g_cnt[b * 32], 1u) == NTb - 1) {
            atomicExch(&g_cnt[b * 32], 0u);
            __threadfence();
            atomicAdd(&g_gen[b * 32], 1u);
        } else {
            while (*genv == cur) { __nanosleep(64); }
            __threadfence();
        }
    }
    __syncthreads();
}

__global__ __launch_bounds__(THREADS, 1) void fused_kernel(
        const float* __restrict__ xp,
        const float* __restrict__ xn_in,
        const void*  __restrict__ mask_raw,
        const int*   __restrict__ am,
        float* out, int ofm) {
    extern __shared__ __align__(16) float dn_s[];    // [Kn][LT] transposed, 64 KB
    __shared__ __align__(16) float bp_s[Kn][4];      // base pred coords (padded)
    __shared__ __align__(16) float bnv_s[Kn][4];     // base native coords (padded)
    __shared__ float red_s[Pn][NW];                  // warp-reduced partials
    __shared__ float ssum_s[Pn];
    __shared__ short pos_s[Ln];
    __shared__ unsigned sig_s[Pn * Kn];              // sigma_j(k) * 1024 (row byte offset)
    __shared__ unsigned char mb_s[Kn];
    __shared__ int bj_s;

    const int tid = threadIdx.x;
    const int lp = tid & (NPAIR - 1);     // l-pair 0..127
    const int kq = tid >> 7;              // 0..7
    const int wid = tid >> 5;
    const int lane = tid & 31;
    const int b = blockIdx.x / NTb;
    const int t = blockIdx.x % NTb;
    const int lg0 = t * LT + 2 * lp;
    const int lg1 = lg0 + 1;

    float* xnat = out;
    float* mkf = out + Bn * Ln * 3;
    unsigned char* mkb = (unsigned char*)(out + Bn * Ln * 3);

    // ---- detect input-mask dtype (deterministic, per block) ----
    int all01 = 1, allf = 1;
    {
        const unsigned* mw = (const unsigned*)mask_raw;
        if (tid < 1024) {
            unsigned w = mw[tid];
            if (w > 1u) all01 = 0;
            if (w != 0u && w != 0x3F800000u) allf = 0;
        }
    }
    all01 = __syncthreads_and(all01);
    allf  = __syncthreads_and(allf);
    const int mode = all01 ? 1 : (allf ? 2 : 0);

    // ---- init: each block seeds its OWN tile slice of out ----
    {
        const float* src = xn_in + (b * Ln + t * LT) * 3;
        float* dst = xnat + (b * Ln + t * LT) * 3;
        if (tid < LT * 3) dst[tid] = src[tid];
        if (kq == 0) {
            #pragma unroll
            for (int h = 0; h < 2; ++h) {
                int i = b * Ln + lg0 + h;
                int v;
                if (mode == 1)      v = ((const int*)mask_raw)[i] != 0;
                else if (mode == 2) v = ((const float*)mask_raw)[i] != 0.0f;
                else                v = ((const unsigned char*)mask_raw)[i] != 0;
                if (ofm) mkf[i] = v ? 1.0f : 0.0f;
                else     mkb[i] = (unsigned char)v;
            }
        }
    }

    batch_sync(b);

    for (int g = 0; g < Gn; ++g) {
        const int* arow = am + g * Pn * Kn;

        if (tid < Ln / 2) ((unsigned*)pos_s)[tid] = 0xFFFFFFFFu;   // pos = -1
        __syncthreads();

        if (tid < Kn) {
            int p0 = __ldg(arow + tid);
            pos_s[p0] = (short)tid;
            const float* q = xp + (b * Ln + p0) * 3;
            bp_s[tid][0] = __ldg(q + 0); bp_s[tid][1] = __ldg(q + 1); bp_s[tid][2] = __ldg(q + 2);
            const float* r = xnat + (b * Ln + p0) * 3;
            bnv_s[tid][0] = r[0]; bnv_s[tid][1] = r[1]; bnv_s[tid][2] = r[2];
            mb_s[tid] = ofm ? (unsigned char)(mkf[b * Ln + p0] != 0.0f)
                            : mkb[b * Ln + p0];
        }
        __syncthreads();

        // sigma_j(k) * (LT*4) = byte offset of dn row (transposed layout)
        if (tid < Pn * Kn) {
            short m = pos_s[__ldg(arow + tid)];
            sig_s[tid] = (unsigned)(m < 0 ? 0 : m) * (LT * 4);
        }
        const float cm0 = (pos_s[lg0] >= 0) ? 0.0f : 1.0f;
        const float cm1 = (pos_s[lg1] >= 0) ? 0.0f : 1.0f;
        // per-group coord loads (L1 hits; keeps register pressure low)
        const float px0 = __ldg(xp + (b * Ln + lg0) * 3 + 0);
        const float py0 = __ldg(xp + (b * Ln + lg0) * 3 + 1);
        const float pz0 = __ldg(xp + (b * Ln + lg0) * 3 + 2);
        const float px1 = __ldg(xp + (b * Ln + lg1) * 3 + 0);
        const float py1 = __ldg(xp + (b * Ln + lg1) * 3 + 1);
        const float pz1 = __ldg(xp + (b * Ln + lg1) * 3 + 2);
        const float nx0 = xnat[(b * Ln + lg0) * 3 + 0];
        const float ny0 = xnat[(b * Ln + lg0) * 3 + 1];
        const float nz0 = xnat[(b * Ln + lg0) * 3 + 2];
        const float nx1 = xnat[(b * Ln + lg1) * 3 + 0];
        const float ny1 = xnat[(b * Ln + lg1) * 3 + 1];
        const float nz1 = xnat[(b * Ln + lg1) * 3 + 2];
        __syncthreads();

        // ---- distances for own k-slice, both l's: dp -> regs, dn -> smem ----
        float dpr[2 * KQ];
        #pragma unroll
        for (int kk = 0; kk < KQ; ++kk) {
            const int k = kq * KQ + kk;
            float4 bp4 = *(const float4*)bp_s[k];
            float dx0 = bp4.x - px0, dy0 = bp4.y - py0, dz0 = bp4.z - pz0;
            dpr[2 * kk + 0] = sqrtf(dx0 * dx0 + dy0 * dy0 + dz0 * dz0);
            float dx1 = bp4.x - px1, dy1 = bp4.y - py1, dz1 = bp4.z - pz1;
            dpr[2 * kk + 1] = sqrtf(dx1 * dx1 + dy1 * dy1 + dz1 * dz1);
            float4 bn4 = *(const float4*)bnv_s[k];
            float ex0 = bn4.x - nx0, ey0 = bn4.y - ny0, ez0 = bn4.z - nz0;
            float ex1 = bn4.x - nx1, ey1 = bn4.y - ny1, ez1 = bn4.z - nz1;
            float2 dn2;
            dn2.x = sqrtf(ex0 * ex0 + ey0 * ey0 + ez0 * ez0);
            dn2.y = sqrtf(ex1 * ex1 + ey1 * ey1 + ez1 * ez1);
            *(float2*)(dn_s + k * LT + 2 * lp) = dn2;
        }
        __syncthreads();   // cross-slice dn row reads below

        // ---- scores: own k-slice, all j; one LDS.64 serves both l's ----
        {
            const char* dn_base = (const char*)dn_s + lp * 8;
            const unsigned* sj = sig_s + kq * KQ;
            #pragma unroll 1
            for (int j = 0; j < Pn; ++j) {
                float a00 = 0.0f, a01 = 0.0f, a10 = 0.0f, a11 = 0.0f;
                #pragma unroll
                for (int kk = 0; kk < KQ; kk += 2) {
                    unsigned offA = sj[j * Kn + kk];
                    unsigned offB = sj[j * Kn + kk + 1];
                    float2 dnA = *(const float2*)(dn_base + offA);
                    float dA0 = dpr[2 * kk + 0] - dnA.x;
                    a00 += fminf(dA0 * dA0, kClamp);
                    float dA1 = dpr[2 * kk + 1] - dnA.y;
                    a01 += fminf(dA1 * dA1, kClamp);
                    float2 dnB = *(const float2*)(dn_base + offB);
                    float dB0 = dpr[2 * kk + 2] - dnB.x;
                    a10 += fminf(dB0 * dB0, kClamp);
                    float dB1 = dpr[2 * kk + 3] - dnB.y;
                    a11 += fminf(dB1 * dB1, kClamp);
                }
                float acc = (a00 + a10) * cm0 + (a01 + a11) * cm1;
                #pragma unroll
                for (int s = 16; s > 0; s >>= 1)
                    acc += __shfl_xor_sync(0xFFFFFFFFu, acc, s);
                if (lane == 0) red_s[j][wid] = acc;
            }
        }
        __syncthreads();

        if (tid < Pn) {
            float v = 0.0f;
            #pragma unroll
            for (int wc = 0; wc < NW; ++wc) v += red_s[tid][wc];
            g_partial[g & 1][b][t][tid] = v;
        }
        batch_sync(b);

        // ---- selection (redundant, bit-identical in every block of b) ----
        if (tid < Pn) {
            float v = 0.0f;
            for (int tt = 0; tt < NTb; ++tt)
                v += vldf(&g_partial[g & 1][b][tt][tid]);
            ssum_s[tid] = v;
        }
        __syncthreads();
        if (tid == 0) {
            float best = ssum_s[0];
            int bi = 0;
            for (int j = 1; j < Pn; ++j)
                if (ssum_s[j] < best) { best = ssum_s[j]; bi = j; }
            bj_s = bi;
        }
        __syncthreads();

        // ---- update (identical writes from every block of b) ----
        if (tid < Kn) {
            int a0i = __ldg(arow + tid);
            int sk = (int)(sig_s[bj_s * Kn + tid] >> 10);   // / (LT*4)
            float* w = xnat + (b * Ln + a0i) * 3;
            w[0] = bnv_s[sk][0]; w[1] = bnv_s[sk][1]; w[2] = bnv_s[sk][2];
            if (ofm) mkf[b * Ln + a0i] = mb_s[sk] ? 1.0f : 0.0f;
            else     mkb[b * Ln + a0i] = mb_s[sk];
        }
        __syncthreads();   // own update writes visible block-wide before next group
    }
}

} // namespace

extern "C" void kernel_launch(void* const* d_in, const int* in_sizes, int n_in,
                              void* d_out, int out_size) {
    const float* xp = (const float*)d_in[0];
    const float* xn = (const float*)d_in[1];
    const void* mask = d_in[2];
    const int* am = (const int*)d_in[3];
    float* out = (float*)d_out;

    (void)in_sizes; (void)n_in;

    const int ofm = (out_size == Bn * Ln * 3 + Bn * Ln) ? 1 : 0;

    cudaFuncSetAttribute(fused_kernel,
                         cudaFuncAttributeMaxDynamicSharedMemorySize, DN_BYTES);
    fused_kernel<<<GRID, THREADS, DN_BYTES>>>(xp, xn, mask, am, out, ofm);
}